// round 1
// baseline (speedup 1.0000x reference)
#include <cuda_runtime.h>
#include <stdint.h>

// ---------------- problem constants ----------------
#define BATCH     16
#define KTOP      5000
#define NBINS     4096        // top-12-bit monotonic float bins
#define CAND_CAP  8192
#define GPB       34527       // 128-elem groups per batch (25920+6480+1620+405+102)
#define BK        (BATCH*KTOP)   // 80000

// level tables (S = 64,32,16,8,4):
//  E   = 810*S*S elems per (level,batch) chunk
//  group offsets within a batch: 0,25920,32400,34020,34425
//  score offset GOFF = anchor_off*90

// ---------------- scratch (no allocation allowed) ----------------
static __device__ unsigned int        d_ghist[BATCH*NBINS];
static __device__ unsigned int        d_thresh[BATCH];
static __device__ unsigned int        d_candcnt[BATCH];
static __device__ unsigned long long  d_cand[BATCH*CAND_CAP];
static __device__ unsigned short      d_gmax[BATCH*GPB];

__device__ __forceinline__ unsigned int ordu(float f) {
    unsigned int u = __float_as_uint(f);
    return (u & 0x80000000u) ? ~u : (u | 0x80000000u);
}

// ---------------- pass 0: zero scratch ----------------
__global__ void k_zero() {
    int i = blockIdx.x * blockDim.x + threadIdx.x;
    if (i < BATCH*NBINS) d_ghist[i] = 0u;
    if (i < BATCH)       d_candcnt[i] = 0u;
}

// ---------------- pass 1: stream cls, group-max + group-max histogram ----------------
__global__ __launch_bounds__(1024, 2) void k_scan(
    const float* __restrict__ c0, const float* __restrict__ c1,
    const float* __restrict__ c2, const float* __restrict__ c3,
    const float* __restrict__ c4)
{
    int b    = blockIdx.y;
    int warp = threadIdx.x >> 5;
    int lane = threadIdx.x & 31;
    for (int wg = blockIdx.x * 32 + warp; wg < GPB; wg += gridDim.x * 32) {
        const float* cp; int E, gi;
        if (wg < 25920)      { cp = c0; E = 3317760; gi = wg;         }
        else if (wg < 32400) { cp = c1; E = 829440;  gi = wg - 25920; }
        else if (wg < 34020) { cp = c2; E = 207360;  gi = wg - 32400; }
        else if (wg < 34425) { cp = c3; E = 51840;   gi = wg - 34020; }
        else                 { cp = c4; E = 12960;   gi = wg - 34425; }
        int m0 = gi * 128 + lane * 4;
        unsigned int mb = 0u;
        const float* p = cp + (size_t)b * E + m0;
        if (m0 + 3 < E) {
            float4 v = *(const float4*)p;
            unsigned int q0 = ordu(v.x) >> 20, q1 = ordu(v.y) >> 20;
            unsigned int q2 = ordu(v.z) >> 20, q3 = ordu(v.w) >> 20;
            mb = max(max(q0, q1), max(q2, q3));
        } else {
            for (int e = 0; e < 4 && m0 + e < E; e++)
                mb = max(mb, ordu(p[e]) >> 20);
        }
        #pragma unroll
        for (int o = 16; o; o >>= 1)
            mb = max(mb, __shfl_xor_sync(0xffffffffu, mb, o));
        if (lane == 0) {
            d_gmax[b * GPB + wg] = (unsigned short)mb;
            atomicAdd(&d_ghist[b * NBINS + mb], 1u);
        }
    }
}

// ---------------- pass 2: per-batch threshold bin from group-max histogram ----------------
__global__ void k_thresh() {
    __shared__ unsigned int ss[1024];
    int b = blockIdx.x;
    int t = threadIdx.x;
    const unsigned int* h = d_ghist + b * NBINS;
    unsigned int s = h[4*t] + h[4*t+1] + h[4*t+2] + h[4*t+3];
    ss[t] = s;
    for (int off = 1; off < 1024; off <<= 1) {
        __syncthreads();
        unsigned int add = (t + off < 1024) ? ss[t + off] : 0u;
        __syncthreads();
        ss[t] += add;
    }
    __syncthreads();
    unsigned int suf_excl = ss[t] - s;   // sum of strictly-higher chunks
    if (suf_excl < (unsigned)KTOP && suf_excl + s >= (unsigned)KTOP) {
        unsigned int acc = suf_excl;
        unsigned int tb = 0u;
        for (int bin = 4*t + 3; bin >= 4*t; --bin) {
            acc += h[bin];
            if (acc >= (unsigned)KTOP) { tb = (unsigned)bin; break; }
        }
        d_thresh[b] = tb;
    }
}

// ---------------- pass 3: compact candidates (skip cold groups) ----------------
__global__ __launch_bounds__(1024, 2) void k_compact(
    const float* __restrict__ c0, const float* __restrict__ c1,
    const float* __restrict__ c2, const float* __restrict__ c3,
    const float* __restrict__ c4)
{
    int b = blockIdx.y;
    unsigned int thr = d_thresh[b];
    int warp = threadIdx.x >> 5;
    int lane = threadIdx.x & 31;
    for (int wg = blockIdx.x * 32 + warp; wg < GPB; wg += gridDim.x * 32) {
        unsigned int gm = d_gmax[b * GPB + wg];
        if (gm < thr) continue;
        const float* cp; int E, gi, s2sh; unsigned int goff;
        if (wg < 25920)      { cp = c0; E = 3317760; gi = wg;         s2sh = 12; goff = 0u;       }
        else if (wg < 32400) { cp = c1; E = 829440;  gi = wg - 25920; s2sh = 10; goff = 3317760u; }
        else if (wg < 34020) { cp = c2; E = 207360;  gi = wg - 32400; s2sh = 8;  goff = 4147200u; }
        else if (wg < 34425) { cp = c3; E = 51840;   gi = wg - 34020; s2sh = 6;  goff = 4354560u; }
        else                 { cp = c4; E = 12960;   gi = wg - 34425; s2sh = 4;  goff = 4406400u; }
        int m0 = gi * 128 + lane * 4;
        const float* p = cp + (size_t)b * E + m0;
        #pragma unroll
        for (int e = 0; e < 4; e++) {
            int m = m0 + e;
            if (m >= E) break;
            unsigned int o = ordu(p[e]);
            if ((o >> 20) >= thr) {
                int ch = m >> s2sh;
                int hw = m & ((1 << s2sh) - 1);
                unsigned int g = goff + (unsigned)hw * 810u + (unsigned)ch;
                unsigned long long key =
                    ((unsigned long long)o << 32) | (unsigned int)(~g);
                unsigned int pos = atomicAdd(&d_candcnt[b], 1u);
                if (pos < CAND_CAP) d_cand[b * CAND_CAP + pos] = key;
            }
        }
    }
}

// ---------------- pass 4: per-batch bitonic sort + decode + gather + emit ----------------
extern __shared__ unsigned long long s_keys[];
__global__ void k_sort(
    const float* __restrict__ b0, const float* __restrict__ b1,
    const float* __restrict__ b2, const float* __restrict__ b3,
    const float* __restrict__ b4, float* __restrict__ out)
{
    int b = blockIdx.x, t = threadIdx.x;
    unsigned int n = d_candcnt[b];
    if (n > CAND_CAP) n = CAND_CAP;
    for (int i = t; i < CAND_CAP; i += 1024)
        s_keys[i] = (i < (int)n) ? d_cand[b * CAND_CAP + i] : 0ull;
    __syncthreads();

    for (unsigned int k = 2; k <= CAND_CAP; k <<= 1) {
        for (unsigned int j = k >> 1; j > 0; j >>= 1) {
            for (unsigned int i = t; i < CAND_CAP; i += 1024) {
                unsigned int ix = i ^ j;
                if (ix > i) {
                    unsigned long long a = s_keys[i], c = s_keys[ix];
                    bool desc = ((i & k) == 0);
                    if ((a < c) == desc) { s_keys[i] = c; s_keys[ix] = a; }
                }
            }
            __syncthreads();
        }
    }

    for (int kk = t; kk < KTOP; kk += 1024) {
        unsigned long long key = s_keys[kk];
        unsigned int o = (unsigned int)(key >> 32);
        unsigned int g = ~((unsigned int)key);
        unsigned int bits = (o & 0x80000000u) ? (o & 0x7fffffffu) : ~o;
        float val = __uint_as_float(bits);
        unsigned int anchor = g / 90u;
        unsigned int cls = g - anchor * 90u;
        const float* bp; unsigned int aoff, S2;
        if (anchor < 36864u)      { bp = b0; aoff = 0u;     S2 = 4096u; }
        else if (anchor < 46080u) { bp = b1; aoff = 36864u; S2 = 1024u; }
        else if (anchor < 48384u) { bp = b2; aoff = 46080u; S2 = 256u;  }
        else if (anchor < 48960u) { bp = b3; aoff = 48384u; S2 = 64u;   }
        else                      { bp = b4; aoff = 48960u; S2 = 16u;   }
        unsigned int la = anchor - aoff;
        unsigned int hw = la / 9u;
        unsigned int a9 = la - hw * 9u;
        size_t base = (size_t)b * 36 * S2 + (size_t)a9 * 4 * S2 + hw;
        int ok = b * KTOP + kk;
        out[ok] = val;                                   // cls_topk  [B,K,1]
        out[BK + 4*ok + 0] = bp[base];                   // box_topk  [B,K,4]
        out[BK + 4*ok + 1] = bp[base +     S2];
        out[BK + 4*ok + 2] = bp[base + 2 * S2];
        out[BK + 4*ok + 3] = bp[base + 3 * S2];
        out[BK * 5 + ok] = (float)anchor;                // indices   [B,K]
        out[BK * 6 + ok] = (float)cls;                   // classes   [B,K]
    }
}

// ---------------- launcher ----------------
extern "C" void kernel_launch(void* const* d_in, const int* in_sizes, int n_in,
                              void* d_out, int out_size)
{
    (void)out_size;
    // Identify inputs by element count (all 10 sizes are distinct).
    static const int csz[5] = {53084160, 13271040, 3317760, 829440, 207360};
    static const int bsz[5] = {2359296,  589824,   147456,  36864,  9216};
    const float* cls[5] = {0,0,0,0,0};
    const float* box[5] = {0,0,0,0,0};
    for (int i = 0; i < n_in; i++) {
        for (int l = 0; l < 5; l++) {
            if (in_sizes[i] == csz[l]) cls[l] = (const float*)d_in[i];
            if (in_sizes[i] == bsz[l]) box[l] = (const float*)d_in[i];
        }
    }

    cudaFuncSetAttribute(k_sort, cudaFuncAttributeMaxDynamicSharedMemorySize,
                         CAND_CAP * sizeof(unsigned long long));

    k_zero<<<256, 256>>>();
    dim3 g(37, BATCH);
    k_scan<<<g, 1024>>>(cls[0], cls[1], cls[2], cls[3], cls[4]);
    k_thresh<<<BATCH, 1024>>>();
    k_compact<<<g, 1024>>>(cls[0], cls[1], cls[2], cls[3], cls[4]);
    k_sort<<<BATCH, 1024, CAND_CAP * sizeof(unsigned long long)>>>(
        box[0], box[1], box[2], box[3], box[4], (float*)d_out);
}